// round 5
// baseline (speedup 1.0000x reference)
#include <cuda_runtime.h>

#define GRID_N   7
#define NB       2
#define NC       20
#define IS       8
#define DCH      30
#define L_BOX    5.0f
#define L_NEG    0.5f

#define TPB      256
#define MAX_BLOCKS 8192

__device__ double g_partials[MAX_BLOCKS];
__device__ unsigned int g_count = 0;

__device__ __forceinline__ float bce_f(float x, float t) {
    return fmaxf(x, 0.0f) - x * t + __logf(1.0f + __expf(-fabsf(x)));
}

__device__ __forceinline__ float box_loss_f(const float* pb, const float* gb) {
    float dx = pb[0] - gb[0];
    float dy = pb[1] - gb[1];
    float sw = sqrtf(fabsf(pb[2])) - sqrtf(gb[2]);
    float sh = sqrtf(fabsf(pb[3])) - sqrtf(gb[3]);
    return dx * dx + dy * dy + sw * sw + sh * sh;
}

__device__ __forceinline__ float cell_loss(const float* __restrict__ pc,
                                           const float* __restrict__ gc,
                                           int cellIdx) {
    // ---- issue all always-needed loads back-to-back (MLP ~10) ----
    const float2* pc2 = reinterpret_cast<const float2*>(pc);
    const float2* gc2 = reinterpret_cast<const float2*>(gc);
    float2 pb0 = pc2[0], pb1 = pc2[1], pb2v = pc2[2], pb3 = pc2[3];
    float2 gb0 = gc2[0], gb1 = gc2[1], gb2v = gc2[2], gb3 = gc2[3];
    float2 pconf = pc2[4];          // p[8], p[9]
    float2 gconf = gc2[4];          // g[8], g[9]

    if (gconf.x > 0.0f) {
        // ================= positive cell =================
        float pv[IS] = {pb0.x, pb0.y, pb1.x, pb1.y, pb2v.x, pb2v.y, pb3.x, pb3.y};
        float gv[IS] = {gb0.x, gb0.y, gb1.x, gb1.y, gb2v.x, gb2v.y, gb3.x, gb3.y};

        // ---- classification: two staged halves for load ILP ----
        const float2* pcl2 = reinterpret_cast<const float2*>(pc + NB * 5);
        const float2* gcl2 = reinterpret_cast<const float2*>(gc + NB * 5);
        float cls = 0.0f;
        {
            float2 a0 = pcl2[0], a1 = pcl2[1], a2 = pcl2[2], a3 = pcl2[3], a4 = pcl2[4];
            float2 b0 = gcl2[0], b1 = gcl2[1], b2 = gcl2[2], b3 = gcl2[3], b4 = gcl2[4];
            cls += bce_f(a0.x, b0.x) + bce_f(a0.y, b0.y);
            cls += bce_f(a1.x, b1.x) + bce_f(a1.y, b1.y);
            cls += bce_f(a2.x, b2.x) + bce_f(a2.y, b2.y);
            cls += bce_f(a3.x, b3.x) + bce_f(a3.y, b3.y);
            cls += bce_f(a4.x, b4.x) + bce_f(a4.y, b4.y);
        }
        {
            float2 a0 = pcl2[5], a1 = pcl2[6], a2 = pcl2[7], a3 = pcl2[8], a4 = pcl2[9];
            float2 b0 = gcl2[5], b1 = gcl2[6], b2 = gcl2[7], b3 = gcl2[8], b4 = gcl2[9];
            cls += bce_f(a0.x, b0.x) + bce_f(a0.y, b0.y);
            cls += bce_f(a1.x, b1.x) + bce_f(a1.y, b1.y);
            cls += bce_f(a2.x, b2.x) + bce_f(a2.y, b2.y);
            cls += bce_f(a3.x, b3.x) + bce_f(a3.y, b3.y);
            cls += bce_f(a4.x, b4.x) + bce_f(a4.y, b4.y);
        }

        // ---- cell coordinates: cr = (col, row) ----
        int cell = cellIdx % (GRID_N * GRID_N);
        float col = (float)(cell % GRID_N);
        float row = (float)(cell / GRID_N);

        // ---- box offsets ----
        float poff[NB][4], gbox[NB][4];
        #pragma unroll
        for (int b = 0; b < NB; b++) {
            poff[b][0] = __fdividef(1.0f, 1.0f + __expf(-pv[4 * b + 0]));
            poff[b][1] = __fdividef(1.0f, 1.0f + __expf(-pv[4 * b + 1]));
            poff[b][2] = pv[4 * b + 2];
            poff[b][3] = pv[4 * b + 3];
            gbox[b][0] = gv[4 * b + 0];
            gbox[b][1] = gv[4 * b + 1];
            gbox[b][2] = gv[4 * b + 2];
            gbox[b][3] = gv[4 * b + 3];
        }

        // ---- ltrb boxes ----
        float pl[NB][4], gl[NB][4];
        #pragma unroll
        for (int b = 0; b < NB; b++) {
            float cx = (poff[b][0] + col) * (1.0f / GRID_N);
            float cy = (poff[b][1] + row) * (1.0f / GRID_N);
            float w  = poff[b][2], h = poff[b][3];
            pl[b][0] = cx - w * 0.5f; pl[b][1] = cy - h * 0.5f;
            pl[b][2] = cx + w * 0.5f; pl[b][3] = cy + h * 0.5f;
            float gx = (gbox[b][0] + col) * (1.0f / GRID_N);
            float gy = (gbox[b][1] + row) * (1.0f / GRID_N);
            float gw = gbox[b][2], gh = gbox[b][3];
            gl[b][0] = gx - gw * 0.5f; gl[b][1] = gy - gh * 0.5f;
            gl[b][2] = gx + gw * 0.5f; gl[b][3] = gy + gh * 0.5f;
        }

        // ---- 2x2 IoU ----
        float iou[NB][NB];
        #pragma unroll
        for (int pi = 0; pi < NB; pi++) {
            #pragma unroll
            for (int gi = 0; gi < NB; gi++) {
                float ltx = fmaxf(pl[pi][0], gl[gi][0]);
                float lty = fmaxf(pl[pi][1], gl[gi][1]);
                float rbx = fminf(pl[pi][2], gl[gi][2]);
                float rby = fminf(pl[pi][3], gl[gi][3]);
                float wx = fmaxf(rbx - ltx, 0.0f);
                float wy = fmaxf(rby - lty, 0.0f);
                float inter = wx * wy;
                float aa = (pl[pi][2] - pl[pi][0]) * (pl[pi][3] - pl[pi][1]);
                float ab = (gl[gi][2] - gl[gi][0]) * (gl[gi][3] - gl[gi][1]);
                iou[pi][gi] = __fdividef(inter, aa + ab - inter + 1e-7f);
            }
        }

        int ind0 = (iou[1][0] > iou[0][0]) ? 1 : 0;
        int ind1 = (iou[1][1] > iou[0][1]) ? 1 : 0;

        bool same_g = (gbox[0][0] == gbox[1][0]) && (gbox[0][1] == gbox[1][1]) &&
                      (gbox[0][2] == gbox[1][2]) && (gbox[0][3] == gbox[1][3]);
        bool same_ind = (ind0 == ind1);

        float box_cell;
        if (same_g) {
            box_cell = box_loss_f(poff[ind0], gbox[0]);
        } else if (same_ind) {
            box_cell = box_loss_f(poff[0], gbox[0]) + box_loss_f(poff[1], gbox[1]);
        } else {
            box_cell = box_loss_f(poff[ind0], gbox[0]) + box_loss_f(poff[ind1], gbox[1]);
        }

        float conf_cell = same_g ? bce_f(ind1 ? pconf.y : pconf.x, 1.0f)
                                 : (bce_f(pconf.x, 1.0f) + bce_f(pconf.y, 1.0f));

        return L_BOX * box_cell + conf_cell + cls;
    } else {
        return L_NEG * (bce_f(pconf.x, 0.0f) + bce_f(pconf.y, 0.0f));
    }
}

__global__ void __launch_bounds__(TPB, 6)
yolo_loss_kernel(const float* __restrict__ p, const float* __restrict__ g,
                 int ncells, float* __restrict__ out, float inv_nb) {
    const int tid = threadIdx.x;
    const int stride = gridDim.x * TPB;
    float acc = 0.0f;

    // grid-stride loop: fixed per-thread summation order (deterministic)
    for (int idx = blockIdx.x * TPB + tid; idx < ncells; idx += stride) {
        acc += cell_loss(p + (size_t)idx * DCH, g + (size_t)idx * DCH, idx);
    }

    // ---- deterministic block reduction ----
    #pragma unroll
    for (int o = 16; o > 0; o >>= 1)
        acc += __shfl_down_sync(0xffffffffu, acc, o);

    __shared__ float warp_sums[TPB / 32];
    int lane = tid & 31;
    int wid  = tid >> 5;
    if (lane == 0) warp_sums[wid] = acc;
    __syncthreads();

    if (tid == 0) {
        float v = 0.0f;
        #pragma unroll
        for (int w = 0; w < TPB / 32; w++) v += warp_sums[w];
        g_partials[blockIdx.x] = (double)v;
    }

    // ---- last-block finalization (deterministic fixed-order sum) ----
    __shared__ bool isLast;
    if (tid == 0) {
        __threadfence();
        unsigned int v = atomicAdd(&g_count, 1u);
        isLast = (v == gridDim.x - 1);
    }
    __syncthreads();

    if (isLast) {
        __shared__ double sh[TPB];
        double s = 0.0;
        for (int i = tid; i < (int)gridDim.x; i += TPB)
            s += g_partials[i];
        sh[tid] = s;
        __syncthreads();
        #pragma unroll
        for (int strideR = TPB / 2; strideR > 0; strideR >>= 1) {
            if (tid < strideR) sh[tid] += sh[tid + strideR];
            __syncthreads();
        }
        if (tid == 0) {
            out[0] = (float)(sh[0] * (double)inv_nb);
            g_count = 0;   // reset for next graph replay
        }
    }
}

extern "C" void kernel_launch(void* const* d_in, const int* in_sizes, int n_in,
                              void* d_out, int out_size) {
    const float* p = (const float*)d_in[0];
    const float* g = (const float*)d_in[1];
    float* out = (float*)d_out;

    int ncells = in_sizes[0] / DCH;                 // B * 49
    int batch  = ncells / (GRID_N * GRID_N);        // B
    int nblocks = (ncells + 2 * TPB - 1) / (2 * TPB);   // ~2 cells per thread
    if (nblocks < 1) nblocks = 1;
    if (nblocks > MAX_BLOCKS) nblocks = MAX_BLOCKS;

    yolo_loss_kernel<<<nblocks, TPB>>>(p, g, ncells, out, 1.0f / (float)batch);
}

// round 6
// speedup vs baseline: 1.6433x; 1.6433x over previous
#include <cuda_runtime.h>

#define GRID_N   7
#define NB       2
#define NC       20
#define IS       8
#define DCH      30
#define L_BOX    5.0f
#define L_NEG    0.5f

#define TPB      256
#define MAX_BLOCKS 8192

__device__ double g_partials[MAX_BLOCKS];
__device__ unsigned int g_count = 0;

// 1 + exp(-|x|)  (the log1p argument term)
__device__ __forceinline__ float bce_t(float x) {
    return 1.0f + __expf(-fabsf(x));
}

__device__ __forceinline__ float box_loss_f(const float* pb, const float* gb) {
    float dx = pb[0] - gb[0];
    float dy = pb[1] - gb[1];
    float sw = sqrtf(fabsf(pb[2])) - sqrtf(gb[2]);
    float sh = sqrtf(fabsf(pb[3])) - sqrtf(gb[3]);
    return dx * dx + dy * dy + sw * sw + sh * sh;
}

__global__ void __launch_bounds__(TPB)
yolo_loss_kernel(const float* __restrict__ p, const float* __restrict__ g,
                 int ncells, float* __restrict__ out, float inv_nb) {
    const int tid = threadIdx.x;
    const int idx = blockIdx.x * TPB + tid;
    float acc = 0.0f;

    if (idx < ncells) {
        const float* pc = p + (size_t)idx * DCH;
        const float* gc = g + (size_t)idx * DCH;
        const float2* pc2 = reinterpret_cast<const float2*>(pc);
        const float2* gc2 = reinterpret_cast<const float2*>(gc);

        // ---- issue all box+conf loads back-to-back (MLP ~10) ----
        float2 pb0 = pc2[0], pb1 = pc2[1], pb2v = pc2[2], pb3 = pc2[3];
        float2 gb0 = gc2[0], gb1 = gc2[1], gb2v = gc2[2], gb3 = gc2[3];
        float2 pconf = pc2[4];          // p[8], p[9]
        float2 gconf = gc2[4];          // g[8], g[9]

        if (gconf.x > 0.0f) {
            // ================= positive cell =================
            float pv[IS] = {pb0.x, pb0.y, pb1.x, pb1.y, pb2v.x, pb2v.y, pb3.x, pb3.y};
            float gv[IS] = {gb0.x, gb0.y, gb1.x, gb1.y, gb2v.x, gb2v.y, gb3.x, gb3.y};

            // ---- classification: linear part + single log of product ----
            const float2* pcl2 = reinterpret_cast<const float2*>(pc + NB * 5);
            const float2* gcl2 = reinterpret_cast<const float2*>(gc + NB * 5);
            float lin = 0.0f;       // sum of max(x,0) - x*t
            float prod = 1.0f;      // product of (1 + e^{-|x|})
            {
                float2 a0 = pcl2[0], a1 = pcl2[1], a2 = pcl2[2], a3 = pcl2[3], a4 = pcl2[4];
                float2 b0 = gcl2[0], b1 = gcl2[1], b2 = gcl2[2], b3 = gcl2[3], b4 = gcl2[4];
                lin += fmaxf(a0.x, 0.f) - a0.x * b0.x + fmaxf(a0.y, 0.f) - a0.y * b0.y;
                lin += fmaxf(a1.x, 0.f) - a1.x * b1.x + fmaxf(a1.y, 0.f) - a1.y * b1.y;
                lin += fmaxf(a2.x, 0.f) - a2.x * b2.x + fmaxf(a2.y, 0.f) - a2.y * b2.y;
                lin += fmaxf(a3.x, 0.f) - a3.x * b3.x + fmaxf(a3.y, 0.f) - a3.y * b3.y;
                lin += fmaxf(a4.x, 0.f) - a4.x * b4.x + fmaxf(a4.y, 0.f) - a4.y * b4.y;
                prod *= bce_t(a0.x) * bce_t(a0.y);
                prod *= bce_t(a1.x) * bce_t(a1.y);
                prod *= bce_t(a2.x) * bce_t(a2.y);
                prod *= bce_t(a3.x) * bce_t(a3.y);
                prod *= bce_t(a4.x) * bce_t(a4.y);
            }
            {
                float2 a0 = pcl2[5], a1 = pcl2[6], a2 = pcl2[7], a3 = pcl2[8], a4 = pcl2[9];
                float2 b0 = gcl2[5], b1 = gcl2[6], b2 = gcl2[7], b3 = gcl2[8], b4 = gcl2[9];
                lin += fmaxf(a0.x, 0.f) - a0.x * b0.x + fmaxf(a0.y, 0.f) - a0.y * b0.y;
                lin += fmaxf(a1.x, 0.f) - a1.x * b1.x + fmaxf(a1.y, 0.f) - a1.y * b1.y;
                lin += fmaxf(a2.x, 0.f) - a2.x * b2.x + fmaxf(a2.y, 0.f) - a2.y * b2.y;
                lin += fmaxf(a3.x, 0.f) - a3.x * b3.x + fmaxf(a3.y, 0.f) - a3.y * b3.y;
                lin += fmaxf(a4.x, 0.f) - a4.x * b4.x + fmaxf(a4.y, 0.f) - a4.y * b4.y;
                prod *= bce_t(a0.x) * bce_t(a0.y);
                prod *= bce_t(a1.x) * bce_t(a1.y);
                prod *= bce_t(a2.x) * bce_t(a2.y);
                prod *= bce_t(a3.x) * bce_t(a3.y);
                prod *= bce_t(a4.x) * bce_t(a4.y);
            }
            float cls = lin + __logf(prod);

            // ---- cell coordinates: cr = (col, row) ----
            int cell = idx % (GRID_N * GRID_N);
            float col = (float)(cell % GRID_N);
            float row = (float)(cell / GRID_N);

            // ---- box offsets ----
            float poff[NB][4], gbox[NB][4];
            #pragma unroll
            for (int b = 0; b < NB; b++) {
                poff[b][0] = __fdividef(1.0f, 1.0f + __expf(-pv[4 * b + 0]));
                poff[b][1] = __fdividef(1.0f, 1.0f + __expf(-pv[4 * b + 1]));
                poff[b][2] = pv[4 * b + 2];
                poff[b][3] = pv[4 * b + 3];
                gbox[b][0] = gv[4 * b + 0];
                gbox[b][1] = gv[4 * b + 1];
                gbox[b][2] = gv[4 * b + 2];
                gbox[b][3] = gv[4 * b + 3];
            }

            // ---- ltrb boxes ----
            float pl[NB][4], gl[NB][4];
            #pragma unroll
            for (int b = 0; b < NB; b++) {
                float cx = (poff[b][0] + col) * (1.0f / GRID_N);
                float cy = (poff[b][1] + row) * (1.0f / GRID_N);
                float w  = poff[b][2], h = poff[b][3];
                pl[b][0] = cx - w * 0.5f; pl[b][1] = cy - h * 0.5f;
                pl[b][2] = cx + w * 0.5f; pl[b][3] = cy + h * 0.5f;
                float gx = (gbox[b][0] + col) * (1.0f / GRID_N);
                float gy = (gbox[b][1] + row) * (1.0f / GRID_N);
                float gw = gbox[b][2], gh = gbox[b][3];
                gl[b][0] = gx - gw * 0.5f; gl[b][1] = gy - gh * 0.5f;
                gl[b][2] = gx + gw * 0.5f; gl[b][3] = gy + gh * 0.5f;
            }

            // ---- 2x2 IoU ----
            float iou[NB][NB];
            #pragma unroll
            for (int pi = 0; pi < NB; pi++) {
                #pragma unroll
                for (int gi = 0; gi < NB; gi++) {
                    float ltx = fmaxf(pl[pi][0], gl[gi][0]);
                    float lty = fmaxf(pl[pi][1], gl[gi][1]);
                    float rbx = fminf(pl[pi][2], gl[gi][2]);
                    float rby = fminf(pl[pi][3], gl[gi][3]);
                    float wx = fmaxf(rbx - ltx, 0.0f);
                    float wy = fmaxf(rby - lty, 0.0f);
                    float inter = wx * wy;
                    float aa = (pl[pi][2] - pl[pi][0]) * (pl[pi][3] - pl[pi][1]);
                    float ab = (gl[gi][2] - gl[gi][0]) * (gl[gi][3] - gl[gi][1]);
                    iou[pi][gi] = __fdividef(inter, aa + ab - inter + 1e-7f);
                }
            }

            int ind0 = (iou[1][0] > iou[0][0]) ? 1 : 0;
            int ind1 = (iou[1][1] > iou[0][1]) ? 1 : 0;

            bool same_g = (gbox[0][0] == gbox[1][0]) && (gbox[0][1] == gbox[1][1]) &&
                          (gbox[0][2] == gbox[1][2]) && (gbox[0][3] == gbox[1][3]);
            bool same_ind = (ind0 == ind1);

            float box_cell;
            if (same_g) {
                box_cell = box_loss_f(poff[ind0], gbox[0]);
            } else if (same_ind) {
                box_cell = box_loss_f(poff[0], gbox[0]) + box_loss_f(poff[1], gbox[1]);
            } else {
                box_cell = box_loss_f(poff[ind0], gbox[0]) + box_loss_f(poff[ind1], gbox[1]);
            }

            // conf: bce(x,1) = max(x,0) - x + log1p(e^-|x|)
            float conf_cell;
            if (same_g) {
                float x = ind1 ? pconf.y : pconf.x;
                conf_cell = fmaxf(x, 0.f) - x + __logf(bce_t(x));
            } else {
                conf_cell = fmaxf(pconf.x, 0.f) - pconf.x + fmaxf(pconf.y, 0.f) - pconf.y
                          + __logf(bce_t(pconf.x) * bce_t(pconf.y));
            }

            acc = L_BOX * box_cell + conf_cell + cls;
        } else {
            // ================= negative cell =================
            // bce(x,0) = max(x,0) + log1p(e^-|x|); merge the two logs
            float negc = fmaxf(pconf.x, 0.f) + fmaxf(pconf.y, 0.f)
                       + __logf(bce_t(pconf.x) * bce_t(pconf.y));
            acc = L_NEG * negc;
        }
    }

    // ---- deterministic block reduction ----
    #pragma unroll
    for (int o = 16; o > 0; o >>= 1)
        acc += __shfl_down_sync(0xffffffffu, acc, o);

    __shared__ float warp_sums[TPB / 32];
    int lane = tid & 31;
    int wid  = tid >> 5;
    if (lane == 0) warp_sums[wid] = acc;
    __syncthreads();

    if (tid == 0) {
        float v = 0.0f;
        #pragma unroll
        for (int w = 0; w < TPB / 32; w++) v += warp_sums[w];
        g_partials[blockIdx.x] = (double)v;
    }

    // ---- last-block finalization (deterministic fixed-order sum) ----
    __shared__ bool isLast;
    if (tid == 0) {
        __threadfence();
        unsigned int v = atomicAdd(&g_count, 1u);
        isLast = (v == gridDim.x - 1);
    }
    __syncthreads();

    if (isLast) {
        __shared__ double sh[TPB];
        double s = 0.0;
        for (int i = tid; i < (int)gridDim.x; i += TPB)
            s += g_partials[i];
        sh[tid] = s;
        __syncthreads();
        #pragma unroll
        for (int strideR = TPB / 2; strideR > 0; strideR >>= 1) {
            if (tid < strideR) sh[tid] += sh[tid + strideR];
            __syncthreads();
        }
        if (tid == 0) {
            out[0] = (float)(sh[0] * (double)inv_nb);
            g_count = 0;   // reset for next graph replay
        }
    }
}

extern "C" void kernel_launch(void* const* d_in, const int* in_sizes, int n_in,
                              void* d_out, int out_size) {
    const float* p = (const float*)d_in[0];
    const float* g = (const float*)d_in[1];
    float* out = (float*)d_out;

    int ncells = in_sizes[0] / DCH;                 // B * 49
    int batch  = ncells / (GRID_N * GRID_N);        // B
    int nblocks = (ncells + TPB - 1) / TPB;

    yolo_loss_kernel<<<nblocks, TPB>>>(p, g, ncells, out, 1.0f / (float)batch);
}